// round 3
// baseline (speedup 1.0000x reference)
#include <cuda_runtime.h>
#include <cuda_bf16.h>
#include <math.h>

#define BSZ 2
#define NP  8192
#define CC  64
#define HH  64
#define WW  160
#define QQ  (HH * WW)   // 10240
#define KNN 3

// ---------------- scratch (device globals; no allocs allowed) ----------------
__device__ float2 g_uvp[BSZ * NP];            // packed (x,y) per point
__device__ float  g_uu [BSZ * NP];            // fl(fl(x*x)+fl(y*y)) per point
__device__ float  g_featT[BSZ * NP * CC];     // feat_3d transposed to [b][n][c]
__device__ float  g_final[BSZ * QQ * CC];     // weighted feature sum [b][q][c]

// ---------------- kernel 0: pack uv + precompute |u|^2 ----------------------
__global__ void pack_uv_kernel(const float* __restrict__ uv) {
    int i = blockIdx.x * blockDim.x + threadIdx.x;   // 0 .. BSZ*NP-1
    int b = i >> 13;          // /NP
    int n = i & (NP - 1);
    float x = uv[(b * 2 + 0) * NP + n];
    float y = uv[(b * 2 + 1) * NP + n];
    g_uvp[i] = make_float2(x, y);
    // exact replica of jnp.sum(uv*uv, axis=1): fl(fl(x*x) + fl(y*y))
    g_uu[i]  = __fadd_rn(__fmul_rn(x, x), __fmul_rn(y, y));
}

// ---------------- kernel 1: transpose feat_3d [b][c][n] -> [b][n][c] ---------
__global__ void transpose_kernel(const float* __restrict__ f3d) {
    __shared__ float tile[32][33];
    int b  = blockIdx.z;
    int n0 = blockIdx.x * 32;
    int c0 = blockIdx.y * 32;
    int tx = threadIdx.x, ty = threadIdx.y;
    tile[ty][tx] = f3d[((b * CC) + c0 + ty) * NP + n0 + tx];
    __syncthreads();
    g_featT[((size_t)(b * NP + n0 + ty)) * CC + c0 + tx] = tile[tx][ty];
}

// ---------------- top-3 insertion (lexicographic on (d, idx)) ----------------
__device__ __forceinline__ void ins3(float d, int i,
                                     float& t0, int& i0,
                                     float& t1, int& i1,
                                     float& t2, int& i2) {
    if (d < t2 || (d == t2 && i < i2)) {
        if (d < t1 || (d == t1 && i < i1)) {
            t2 = t1; i2 = i1;
            if (d < t0 || (d == t0 && i < i0)) {
                t1 = t0; i1 = i0;
                t0 = d;  i0 = i;
            } else {
                t1 = d;  i1 = i;
            }
        } else {
            t2 = d; i2 = i;
        }
    }
}

// ---------------- kernel 2: KNN scan + score MLP + weighted gather -----------
// Block: 256 threads = 32 pixels x 8 lanes. Each lane scans points
// n = {sub, sub+8, ...} x2 (float4 = 2 points), keeps register top-3,
// butterfly-merges within the 8-lane group, then handles 8 interleaved
// channels (c = 8*cc + sub) of the weighted feature sum.
__global__ __launch_bounds__(256) void knn_mlp_kernel(
    const float* __restrict__ w1, const float* __restrict__ b1,
    const float* __restrict__ w2, const float* __restrict__ b2) {

    __shared__ float s_w1[48];
    __shared__ float s_b1[16];
    __shared__ float s_w2j[16 * 64];   // j-major: s_w2j[j*64 + c] = w2[c*16 + j]
    __shared__ float s_b2[64];

    int tid = threadIdx.x;
    if (tid < 48) s_w1[tid] = w1[tid];
    if (tid < 16) s_b1[tid] = b1[tid];
    for (int i = tid; i < 1024; i += 256) {
        int c = i >> 4, j = i & 15;
        s_w2j[j * 64 + c] = w2[i];
    }
    if (tid < 64) s_b2[tid] = b2[tid];
    __syncthreads();

    int blk = blockIdx.x;
    int b   = blk / (QQ / 32);
    int q   = (blk % (QQ / 32)) * 32 + (tid >> 3);
    int sub = tid & 7;

    float fgx = (float)(q % WW);
    float fgy = (float)(q / WW);

    // exact replica of jnp.sum(grid*grid, axis=1): fl(fl(gx*gx) + fl(gy*gy))
    float gg = __fadd_rn(__fmul_rn(fgx, fgx), __fmul_rn(fgy, fgy));

    // ---- phase 1: brute-force scan, 2 points per iteration ----
    // d2 must bit-match the reference:
    //   d2 = fl( fl(gg + uu) - 2 * fma(gy*uy, fl(gx*ux)) )
    const float4* uv4 = (const float4*)(g_uvp + b * NP);
    const float2* uu2 = (const float2*)(g_uu  + b * NP);
    float t0 = 1e30f, t1 = 1e30f, t2 = 1e30f;
    int   i0 = NP,    i1 = NP,    i2 = NP;

    #pragma unroll 4
    for (int j = sub; j < NP / 2; j += 8) {
        float4 p = __ldg(&uv4[j]);
        float2 u = __ldg(&uu2[j]);
        float dot0 = __fmaf_rn(p.y, fgy, __fmul_rn(p.x, fgx));
        float d0   = __fmaf_rn(-2.0f, dot0, __fadd_rn(gg, u.x));
        float dot1 = __fmaf_rn(p.w, fgy, __fmul_rn(p.z, fgx));
        float d1   = __fmaf_rn(-2.0f, dot1, __fadd_rn(gg, u.y));
        if (d0 <= t2) ins3(d0, 2 * j,     t0, i0, t1, i1, t2, i2);
        if (d1 <= t2) ins3(d1, 2 * j + 1, t0, i0, t1, i1, t2, i2);
    }

    // ---- merge top-3 across the 8-lane group (butterfly) ----
    #pragma unroll
    for (int off = 1; off < 8; off <<= 1) {
        float o0 = __shfl_xor_sync(0xffffffffu, t0, off);
        float o1 = __shfl_xor_sync(0xffffffffu, t1, off);
        float o2 = __shfl_xor_sync(0xffffffffu, t2, off);
        int   j0 = __shfl_xor_sync(0xffffffffu, i0, off);
        int   j1 = __shfl_xor_sync(0xffffffffu, i1, off);
        int   j2 = __shfl_xor_sync(0xffffffffu, i2, off);
        ins3(o0, j0, t0, i0, t1, i1, t2, i2);
        ins3(o1, j1, t0, i0, t1, i1, t2, i2);
        ins3(o2, j2, t0, i0, t1, i1, t2, i2);
    }

    // ---- phase 2: score MLP + weighted feature accumulation ----
    int kidx[KNN] = { i0, i1, i2 };
    float acc[8];
    #pragma unroll
    for (int cc = 0; cc < 8; cc++) acc[cc] = 0.f;

    #pragma unroll
    for (int k = 0; k < KNN; k++) {
        int n = kidx[k];
        float2 p = __ldg(&g_uvp[b * NP + n]);
        float ox = p.x - fgx;
        float oy = p.y - fgy;
        float nr = sqrtf(ox * ox + oy * oy);

        float h[16];
        #pragma unroll
        for (int j = 0; j < 16; j++) {
            float z = fmaf(s_w1[j * 3 + 0], ox,
                      fmaf(s_w1[j * 3 + 1], oy,
                      fmaf(s_w1[j * 3 + 2], nr, s_b1[j])));
            h[j] = fmaxf(z, 0.f);
        }

        const float* fptr = g_featT + ((size_t)(b * NP + n)) * CC;
        #pragma unroll
        for (int cc = 0; cc < 8; cc++) {
            int c = cc * 8 + sub;     // interleaved -> conflict-free smem banks
            float z = s_b2[c];
            #pragma unroll
            for (int j = 0; j < 16; j++)
                z = fmaf(s_w2j[j * 64 + c], h[j], z);
            float sc = __fdividef(1.f, 1.f + __expf(-z));
            acc[cc] = fmaf(sc, __ldg(&fptr[c]), acc[cc]);
        }
    }

    float* dst = g_final + ((size_t)(b * QQ + q)) * CC;
    #pragma unroll
    for (int cc = 0; cc < 8; cc++)
        dst[cc * 8 + sub] = acc[cc];
}

// ---------------- kernel 3: out = relu(w3 @ final + b3), channel-major -------
// Block: 256 threads, 32 pixels. lane = pixel, warp picks 8 output channels.
__global__ __launch_bounds__(256) void out_gemm_kernel(
    const float* __restrict__ w3, const float* __restrict__ b3,
    float* __restrict__ out) {

    __shared__ float s_w3[64 * 64];
    __shared__ float s_b3[64];
    __shared__ float s_fin[32 * 65];   // pad to 65 -> conflict-free column reads

    int tid = threadIdx.x;
    int blk = blockIdx.x;
    int b   = blk / (QQ / 32);
    int q0  = (blk % (QQ / 32)) * 32;

    for (int i = tid; i < 4096; i += 256) s_w3[i] = w3[i];
    if (tid < 64) s_b3[tid] = b3[tid];
    const float* src = g_final + ((size_t)(b * QQ + q0)) * CC;
    for (int i = tid; i < 2048; i += 256)
        s_fin[(i >> 6) * 65 + (i & 63)] = src[i];
    __syncthreads();

    int lane = tid & 31;
    int wrp  = tid >> 5;

    float ffin[64];
    #pragma unroll
    for (int c = 0; c < 64; c++) ffin[c] = s_fin[lane * 65 + c];

    int q = q0 + lane;
    #pragma unroll
    for (int oo = 0; oo < 8; oo++) {
        int o = wrp * 8 + oo;
        float acc = s_b3[o];
        #pragma unroll
        for (int c = 0; c < 64; c += 4) {
            float4 wv = *(const float4*)&s_w3[o * 64 + c];
            acc = fmaf(wv.x, ffin[c + 0],
                  fmaf(wv.y, ffin[c + 1],
                  fmaf(wv.z, ffin[c + 2],
                  fmaf(wv.w, ffin[c + 3], acc))));
        }
        out[((size_t)(b * CC + o)) * QQ + q] = fmaxf(acc, 0.f);
    }
}

// ---------------- launch ----------------
extern "C" void kernel_launch(void* const* d_in, const int* in_sizes, int n_in,
                              void* d_out, int out_size) {
    const float* uv  = (const float*)d_in[0];
    // d_in[1] = feat_2d: only its shape is used by the reference; data unused.
    const float* f3d = (const float*)d_in[2];
    const float* w1  = (const float*)d_in[3];
    const float* b1  = (const float*)d_in[4];
    const float* w2  = (const float*)d_in[5];
    const float* b2  = (const float*)d_in[6];
    const float* w3  = (const float*)d_in[7];
    const float* b3  = (const float*)d_in[8];
    float* out = (float*)d_out;

    pack_uv_kernel<<<(BSZ * NP) / 256, 256>>>(uv);

    dim3 tgrid(NP / 32, CC / 32, BSZ);
    transpose_kernel<<<tgrid, dim3(32, 32)>>>(f3d);

    knn_mlp_kernel<<<BSZ * (QQ / 32), 256>>>(w1, b1, w2, b2);

    out_gemm_kernel<<<BSZ * (QQ / 32), 256>>>(w3, b3, out);
}

// round 16
// speedup vs baseline: 4.1011x; 4.1011x over previous
#include <cuda_runtime.h>
#include <cuda_bf16.h>
#include <math.h>

#define BSZ 2
#define NP  8192
#define CC  64
#define HH  64
#define WW  160
#define QQ  (HH * WW)   // 10240
#define KNN 3

#define CS    4                  // cell size in pixels
#define GCX   (WW / CS)          // 40
#define GCY   (HH / CS)          // 16
#define NCELL (GCX * GCY)        // 640
#define EPS_D2 1.0f              // slack >> reference d2 rounding noise (~0.03)

// ---------------- scratch (device globals; no allocs allowed) ----------------
__device__ float2 g_uvp[BSZ * NP];             // (x,y) per point, original order
__device__ float  g_featT[BSZ * NP * CC];      // feat_3d transposed to [b][n][c]
__device__ int    g_cnt   [BSZ * NCELL];       // per-cell counts
__device__ int    g_cellid[BSZ * NP];
__device__ int    g_rank  [BSZ * NP];
__device__ int    g_startA[BSZ * (NCELL + 1)]; // exclusive prefix, +1 sentinel
__device__ float4 g_pts   [BSZ * NP];          // sorted: (x, y, uu, idx-bits)

// ---------------- kernel A: zero counts -------------------------------------
__global__ void zero_cnt_kernel() {
    int i = blockIdx.x * blockDim.x + threadIdx.x;
    if (i < BSZ * NCELL) g_cnt[i] = 0;
}

// ---------------- kernel B: pack uv + histogram -----------------------------
__global__ void pack_bin_kernel(const float* __restrict__ uv) {
    int i = blockIdx.x * blockDim.x + threadIdx.x;   // 0 .. BSZ*NP-1
    int b = i >> 13;
    int n = i & (NP - 1);
    float x = uv[(b * 2 + 0) * NP + n];
    float y = uv[(b * 2 + 1) * NP + n];
    g_uvp[i] = make_float2(x, y);
    int cx = min((int)x / CS, GCX - 1);
    int cy = min((int)y / CS, GCY - 1);
    int cell = cy * GCX + cx;
    g_cellid[i] = cell;
    g_rank[i] = atomicAdd(&g_cnt[b * NCELL + cell], 1);
}

// ---------------- kernel C: prefix scan per batch ---------------------------
__global__ void scan_kernel() {          // grid = BSZ, block = 1024
    __shared__ int buf[1024];
    int b = blockIdx.x, t = threadIdx.x;
    int v = (t < NCELL) ? g_cnt[b * NCELL + t] : 0;
    buf[t] = v;
    __syncthreads();
    for (int off = 1; off < 1024; off <<= 1) {
        int x = (t >= off) ? buf[t - off] : 0;
        __syncthreads();
        buf[t] += x;
        __syncthreads();
    }
    if (t < NCELL) g_startA[b * (NCELL + 1) + t + 1] = buf[t];
    if (t == 0)    g_startA[b * (NCELL + 1)] = 0;
}

// ---------------- kernel D: scatter points into sorted order ----------------
__global__ void scatter_kernel() {
    int i = blockIdx.x * blockDim.x + threadIdx.x;
    int b = i >> 13;
    int n = i & (NP - 1);
    float2 p = g_uvp[i];
    // exact replica of jnp.sum(uv*uv, axis=1): fl(fl(x*x) + fl(y*y))
    float uu = __fadd_rn(__fmul_rn(p.x, p.x), __fmul_rn(p.y, p.y));
    int cell = g_cellid[i];
    int pos  = g_startA[b * (NCELL + 1) + cell] + g_rank[i];
    g_pts[b * NP + pos] = make_float4(p.x, p.y, uu, __int_as_float(n));
}

// ---------------- kernel E: transpose feat_3d [b][c][n] -> [b][n][c] --------
__global__ void transpose_kernel(const float* __restrict__ f3d) {
    __shared__ float tile[32][33];
    int b  = blockIdx.z;
    int n0 = blockIdx.x * 32;
    int c0 = blockIdx.y * 32;
    int tx = threadIdx.x, ty = threadIdx.y;
    tile[ty][tx] = f3d[((b * CC) + c0 + ty) * NP + n0 + tx];
    __syncthreads();
    g_featT[((size_t)(b * NP + n0 + ty)) * CC + c0 + tx] = tile[tx][ty];
}

// ---------------- top-3 insertion (lexicographic on (d, idx)) ----------------
__device__ __forceinline__ void ins3(float d, int i,
                                     float& t0, int& i0,
                                     float& t1, int& i1,
                                     float& t2, int& i2) {
    if (d < t2 || (d == t2 && i < i2)) {
        if (d < t1 || (d == t1 && i < i1)) {
            t2 = t1; i2 = i1;
            if (d < t0 || (d == t0 && i < i0)) {
                t1 = t0; i1 = i0;
                t0 = d;  i0 = i;
            } else {
                t1 = d;  i1 = i;
            }
        } else {
            t2 = d; i2 = i;
        }
    }
}

// scan a contiguous span [s,e) of sorted points, lane-strided by 8
__device__ __forceinline__ void scan_span(const float4* __restrict__ pts,
                                          int s, int e, int sub,
                                          float fgx, float fgy, float gg,
                                          float& t0, int& i0,
                                          float& t1, int& i1,
                                          float& t2, int& i2) {
    for (int j = s + sub; j < e; j += 8) {
        float4 pt = __ldg(&pts[j]);
        // bit-exact replica of reference d2:
        //   fl( fl(gg + uu) - 2 * fma(uy*gy, fl(ux*gx)) )
        float dot = __fmaf_rn(pt.y, fgy, __fmul_rn(pt.x, fgx));
        float d   = __fmaf_rn(-2.0f, dot, __fadd_rn(gg, pt.z));
        if (d <= t2) ins3(d, __float_as_int(pt.w), t0, i0, t1, i1, t2, i2);
    }
}

// ---------------- kernel F: binned KNN + score MLP + fused output GEMM ------
// 256 threads = 32 pixels x 8 lanes. Phase 1: ring scan over cells.
// Phase 2: score MLP, weighted feature sum into smem. Phase 3: remap threads,
// 64x64 projection + relu, write output directly.
__global__ __launch_bounds__(256) void knn_fused_kernel(
    const float* __restrict__ w1, const float* __restrict__ b1,
    const float* __restrict__ w2, const float* __restrict__ b2,
    const float* __restrict__ w3, const float* __restrict__ b3,
    float* __restrict__ out) {

    __shared__ float s_w1[48];
    __shared__ float s_b1[16];
    __shared__ float s_w2j[16 * 64];    // j-major: [j*64 + c] = w2[c*16 + j]
    __shared__ float s_b2[64];
    __shared__ float s_w3[64 * 64];
    __shared__ float s_b3[64];
    __shared__ float s_fin[32 * 68];    // row-pad 68 -> conflict-free float4
    __shared__ int   s_start[NCELL + 1];

    int tid = threadIdx.x;
    int blk = blockIdx.x;
    int b   = blk / (QQ / 32);
    int q0  = (blk % (QQ / 32)) * 32;

    if (tid < 48) s_w1[tid] = w1[tid];
    if (tid < 16) s_b1[tid] = b1[tid];
    for (int i = tid; i < 1024; i += 256) {
        int c = i >> 4, j = i & 15;
        s_w2j[j * 64 + c] = w2[i];
    }
    if (tid < 64) { s_b2[tid] = b2[tid]; s_b3[tid] = b3[tid]; }
    for (int i = tid; i < 4096; i += 256) s_w3[i] = w3[i];
    for (int i = tid; i < NCELL + 1; i += 256)
        s_start[i] = g_startA[b * (NCELL + 1) + i];
    __syncthreads();

    int g    = tid >> 3;         // pixel group 0..31
    int sub  = tid & 7;
    int lane = tid & 31;
    unsigned gmask = 0xFFu << (lane & 24);   // this 8-lane group's mask

    int q  = q0 + g;
    int gx = q % WW, gy = q / WW;
    float fgx = (float)gx, fgy = (float)gy;
    // exact replica of jnp.sum(grid*grid, axis=1)
    float gg = __fadd_rn(__fmul_rn(fgx, fgx), __fmul_rn(fgy, fgy));
    int cx = gx >> 2, cy = gy >> 2;

    const float4* pts = g_pts + b * NP;

    float t0 = 1e30f, t1 = 1e30f, t2 = 1e30f;
    int   i0 = NP,    i1 = NP,    i2 = NP;

    // ---- phase 1: expanding Chebyshev rings of cells ----
    for (int r = 0; r < 64; r++) {
        int xlo = cx - r, xhi = cx + r, ylo = cy - r, yhi = cy + r;
        int xa = max(xlo, 0), xb = min(xhi, GCX - 1);
        if (ylo >= 0) {   // top row (covers r==0 single cell)
            scan_span(pts, s_start[ylo * GCX + xa], s_start[ylo * GCX + xb + 1],
                      sub, fgx, fgy, gg, t0, i0, t1, i1, t2, i2);
        }
        if (r > 0) {
            if (yhi < GCY) {   // bottom row
                scan_span(pts, s_start[yhi * GCX + xa], s_start[yhi * GCX + xb + 1],
                          sub, fgx, fgy, gg, t0, i0, t1, i1, t2, i2);
            }
            int ya = max(ylo + 1, 0), yb = min(yhi - 1, GCY - 1);
            if (xlo >= 0)
                for (int y = ya; y <= yb; y++)
                    scan_span(pts, s_start[y * GCX + xlo], s_start[y * GCX + xlo + 1],
                              sub, fgx, fgy, gg, t0, i0, t1, i1, t2, i2);
            if (xhi < GCX)
                for (int y = ya; y <= yb; y++)
                    scan_span(pts, s_start[y * GCX + xhi], s_start[y * GCX + xhi + 1],
                              sub, fgx, fgy, gg, t0, i0, t1, i1, t2, i2);
        }
        // group-wide upper bound on the true 3rd-best d2
        float U = t2;
        U = fminf(U, __shfl_xor_sync(gmask, U, 1));
        U = fminf(U, __shfl_xor_sync(gmask, U, 2));
        U = fminf(U, __shfl_xor_sync(gmask, U, 4));
        // geometric distance to nearest unscanned region (grid edges free)
        float bound = 1e30f;
        if (xlo > 0)       bound = fminf(bound, fgx - (float)(xlo * CS));
        if (xhi < GCX - 1) bound = fminf(bound, (float)((xhi + 1) * CS) - fgx);
        if (ylo > 0)       bound = fminf(bound, fgy - (float)(ylo * CS));
        if (yhi < GCY - 1) bound = fminf(bound, (float)((yhi + 1) * CS) - fgy);
        if (bound * bound > U + EPS_D2) break;   // also fires when fully scanned
    }

    // ---- merge top-3 across the 8-lane group (disjoint sets -> no dups) ----
    #pragma unroll
    for (int off = 1; off < 8; off <<= 1) {
        float o0 = __shfl_xor_sync(gmask, t0, off);
        float o1 = __shfl_xor_sync(gmask, t1, off);
        float o2 = __shfl_xor_sync(gmask, t2, off);
        int   j0 = __shfl_xor_sync(gmask, i0, off);
        int   j1 = __shfl_xor_sync(gmask, i1, off);
        int   j2 = __shfl_xor_sync(gmask, i2, off);
        ins3(o0, j0, t0, i0, t1, i1, t2, i2);
        ins3(o1, j1, t0, i0, t1, i1, t2, i2);
        ins3(o2, j2, t0, i0, t1, i1, t2, i2);
    }

    // ---- phase 2: score MLP + weighted feature accumulation ----
    int kidx[KNN] = { i0, i1, i2 };
    float acc[8];
    #pragma unroll
    for (int cc = 0; cc < 8; cc++) acc[cc] = 0.f;

    #pragma unroll
    for (int k = 0; k < KNN; k++) {
        int n = kidx[k];
        float2 p = __ldg(&g_uvp[b * NP + n]);
        float ox = p.x - fgx;
        float oy = p.y - fgy;
        float nr = sqrtf(ox * ox + oy * oy);

        float h[16];
        #pragma unroll
        for (int j = 0; j < 16; j++) {
            float z = fmaf(s_w1[j * 3 + 0], ox,
                      fmaf(s_w1[j * 3 + 1], oy,
                      fmaf(s_w1[j * 3 + 2], nr, s_b1[j])));
            h[j] = fmaxf(z, 0.f);
        }

        const float* fptr = g_featT + ((size_t)(b * NP + n)) * CC;
        #pragma unroll
        for (int cc = 0; cc < 8; cc++) {
            int c = cc * 8 + sub;     // interleaved -> conflict-free smem banks
            float z = s_b2[c];
            #pragma unroll
            for (int j = 0; j < 16; j++)
                z = fmaf(s_w2j[j * 64 + c], h[j], z);
            float sc = __fdividef(1.f, 1.f + __expf(-z));
            acc[cc] = fmaf(sc, __ldg(&fptr[c]), acc[cc]);
        }
    }

    #pragma unroll
    for (int cc = 0; cc < 8; cc++)
        s_fin[g * 68 + cc * 8 + sub] = acc[cc];
    __syncthreads();

    // ---- phase 3: fused out = relu(w3 @ final + b3) ----
    // remap: lane = pixel (0..31), warp = 8 output channels
    int wrp = tid >> 5;
    int qq  = q0 + lane;
    float res[8];
    #pragma unroll
    for (int oo = 0; oo < 8; oo++) res[oo] = s_b3[wrp * 8 + oo];
    #pragma unroll
    for (int c4 = 0; c4 < 64; c4 += 4) {
        float4 f = *(const float4*)&s_fin[lane * 68 + c4];
        #pragma unroll
        for (int oo = 0; oo < 8; oo++) {
            float4 wv = *(const float4*)&s_w3[(wrp * 8 + oo) * 64 + c4];
            res[oo] = fmaf(wv.x, f.x,
                      fmaf(wv.y, f.y,
                      fmaf(wv.z, f.z,
                      fmaf(wv.w, f.w, res[oo]))));
        }
    }
    #pragma unroll
    for (int oo = 0; oo < 8; oo++)
        out[((size_t)(b * CC + wrp * 8 + oo)) * QQ + qq] = fmaxf(res[oo], 0.f);
}

// ---------------- launch ----------------
extern "C" void kernel_launch(void* const* d_in, const int* in_sizes, int n_in,
                              void* d_out, int out_size) {
    const float* uv  = (const float*)d_in[0];
    // d_in[1] = feat_2d: only its shape matters to the reference; data unused.
    const float* f3d = (const float*)d_in[2];
    const float* w1  = (const float*)d_in[3];
    const float* b1  = (const float*)d_in[4];
    const float* w2  = (const float*)d_in[5];
    const float* b2  = (const float*)d_in[6];
    const float* w3  = (const float*)d_in[7];
    const float* b3  = (const float*)d_in[8];
    float* out = (float*)d_out;

    zero_cnt_kernel<<<(BSZ * NCELL + 255) / 256, 256>>>();
    pack_bin_kernel<<<(BSZ * NP) / 256, 256>>>(uv);
    scan_kernel<<<BSZ, 1024>>>();
    scatter_kernel<<<(BSZ * NP) / 256, 256>>>();

    dim3 tgrid(NP / 32, CC / 32, BSZ);
    transpose_kernel<<<tgrid, dim3(32, 32)>>>(f3d);

    knn_fused_kernel<<<BSZ * (QQ / 32), 256>>>(w1, b1, w2, b2, w3, b3, out);
}